// round 2
// baseline (speedup 1.0000x reference)
#include <cuda_runtime.h>
#include <math.h>
#include <stdint.h>

#define XP    16386
#define XS    16512          // row stride (129*128)
#define NXV   16384
#define KPAD  16416          // 17 K-slices: 16*1024 + 32
#define NB    16
#define WCH   64
#define HCH   128

// ------------------- static device buffers -------------------
__device__ float d_h   [(size_t)NB * WCH * XS];
__device__ float d_g   [(size_t)NB * WCH * XS];
__device__ float d_gmid[(size_t)NB * HCH * XS];
__device__ float d_wout[(size_t)NB * WCH * XS];
__device__ float d_ftab[(size_t)KPAD * 128];     // [x][2m]=cos, [2m+1]=-sin
__device__ float d_itab[(size_t)128 * XS];       // [2m][x]=cos, [2m+1][x]=sin
__device__ float d_part[(size_t)17 * 2048 * 128];
__device__ float d_fw  [2048 * 128];             // rows 0..1023 v_hat(h), 1024..2047 g_hat
__device__ float d_outm[1024 * 128];             // scaled inverse-DFT coefficients
__device__ float d_w1T [4 * 64 * 128];
__device__ float d_w2T [4 * 128 * 64];
__device__ float d_wwT [4 * 64 * 64];
__device__ float d_fc1T[64 * 128];

// ------------------- helpers -------------------
__device__ __forceinline__ float softplus_(float x) {
    return (x > 20.f) ? x : log1pf(expf(x));
}
__device__ __forceinline__ float gelu_(float v) {
    return 0.5f * v * (1.0f + erff(v * 0.70710678118654752f));
}

// ------------------- table init -------------------
__global__ void init_ftab_kernel() {
    int idx = blockIdx.x * 256 + threadIdx.x;
    if (idx >= KPAD * 128) return;
    int x = idx >> 7, t = idx & 127, m = t >> 1;
    float v = 0.f;
    if (x < XP) {
        int u = (x * m) % XP;
        double s, c;
        sincospi(2.0 * (double)u / (double)XP, &s, &c);
        v = (t & 1) ? (float)(-s) : (float)c;
    }
    d_ftab[idx] = v;
}

__global__ void init_itab_kernel() {
    int idx = blockIdx.x * 256 + threadIdx.x;
    if (idx >= 128 * XS) return;
    int t = idx / XS, x = idx - t * XS, m = t >> 1;
    float v = 0.f;
    if (x < XP) {
        int u = (x * m) % XP;
        double s, c;
        sincospi(2.0 * (double)u / (double)XP, &s, &c);
        v = (t & 1) ? (float)s : (float)c;
    }
    d_itab[idx] = v;
}

// ------------------- weight transposes -------------------
__global__ void prep_weights_kernel(const float* __restrict__ g_w1,
                                    const float* __restrict__ g_w2,
                                    const float* __restrict__ w_w,
                                    const float* __restrict__ fc1_w) {
    int idx = blockIdx.x * 256 + threadIdx.x;
    if (idx < 32768) {                           // w1T[i][c][j] = g_w1[i][j][c]
        int i = idx >> 13, r = idx & 8191, c = r >> 7, j = r & 127;
        d_w1T[idx] = g_w1[(i * 128 + j) * 64 + c];
    } else if (idx < 65536) {                    // w2T[i][j][o] = g_w2[i][o][j]
        int t = idx - 32768;
        int i = t >> 13, r = t & 8191, j = r >> 6, o = r & 63;
        d_w2T[t] = g_w2[(i * 64 + o) * 128 + j];
    } else if (idx < 81920) {                    // wwT[i][c][o] = w_w[i][o][c]
        int t = idx - 65536;
        int i = t >> 12, r = t & 4095, c = r >> 6, o = r & 63;
        d_wwT[t] = w_w[(i * 64 + o) * 64 + c];
    } else if (idx < 90112) {                    // fc1T[c][j] = fc1_w[j][c]
        int t = idx - 81920;
        int c = t >> 7, j = t & 127;
        d_fc1T[t] = fc1_w[j * 64 + c];
    }
}

__global__ void zero_tail_kernel() {
    int idx = blockIdx.x * 256 + threadIdx.x;    // 1024 rows x 128 tail cols
    int row = idx >> 7, col = NXV + (idx & 127);
    d_h[(size_t)row * XS + col] = 0.f;
}

// ------------------- fc0 -------------------
__global__ void __launch_bounds__(128) fc0_kernel(const float* __restrict__ xin,
                                                  const float* __restrict__ gin,
                                                  const float* __restrict__ w,
                                                  const float* __restrict__ bias) {
    __shared__ float sw[64 * 32];
    __shared__ float sb[64];
    int tid = threadIdx.x;
    for (int l = tid; l < 64 * 31; l += 128) {
        int wo = l / 31, c = l - wo * 31;
        sw[wo * 32 + c] = w[l];
    }
    if (tid < 64) sb[tid] = bias[tid];
    __syncthreads();
    int b = blockIdx.y;
    int x = blockIdx.x * 128 + tid;
    float rin[31];
    const float* xi = xin + ((size_t)b * NXV + x) * 30;
#pragma unroll
    for (int c = 0; c < 30; c++) rin[c] = __ldg(&xi[c]);
    rin[30] = __ldg(&gin[(size_t)b * NXV + x]);
    for (int wo = 0; wo < 64; wo++) {
        float acc = sb[wo];
#pragma unroll
        for (int c = 0; c < 31; c++) acc = fmaf(rin[c], sw[wo * 32 + c], acc);
        d_h[(size_t)(b * 64 + wo) * XS + x] = acc;
    }
}

// ------------------- generic 1x1 conv -------------------
// ACT: 0=none, 1=gelu, 2=scale by softplus(*alpha) after bias
template<int CIN, int COUT, int ACT>
__global__ void __launch_bounds__(256) conv1x1_kernel(
    const float* __restrict__ in,    // [b*CIN + c][XS]
    const float* __restrict__ wT,    // [CIN][COUT]
    const float* __restrict__ bias,  // [COUT]
    float* __restrict__ out,         // [b*COUT + o][XS]
    const float* __restrict__ alpha)
{
    constexpr int TO = COUT / 8;
    __shared__ float si [16][128];
    __shared__ float swt[16][COUT];
    const int b   = blockIdx.y;
    const int p0  = blockIdx.x * 128;
    const int tid = threadIdx.x;
    const int po  = (tid & 31) * 4;
    const int oo  = (tid >> 5) * TO;

    float acc[TO][4];
#pragma unroll
    for (int o = 0; o < TO; o++)
#pragma unroll
        for (int p = 0; p < 4; p++) acc[o][p] = 0.f;

    const float* inb = in + (size_t)b * CIN * XS + p0;
    for (int c0 = 0; c0 < CIN; c0 += 16) {
        __syncthreads();
#pragma unroll
        for (int l = 0; l < 8; l++) {
            int idx = l * 256 + tid;
            int k = idx >> 7, p = idx & 127;
            si[k][p] = inb[(size_t)(c0 + k) * XS + p];
        }
#pragma unroll
        for (int l = 0; l < (16 * COUT) / 256; l++) {
            int idx = l * 256 + tid;
            int k = idx / COUT, o = idx - k * COUT;
            swt[k][o] = wT[(size_t)(c0 + k) * COUT + o];
        }
        __syncthreads();
#pragma unroll
        for (int k = 0; k < 16; k++) {
            float4 av = *(const float4*)&si[k][po];
            float avs[4] = {av.x, av.y, av.z, av.w};
#pragma unroll
            for (int og = 0; og < TO / 4; og++) {
                float4 wv = *(const float4*)&swt[k][oo + og * 4];
                float wvs[4] = {wv.x, wv.y, wv.z, wv.w};
#pragma unroll
                for (int j = 0; j < 4; j++)
#pragma unroll
                    for (int p = 0; p < 4; p++)
                        acc[og * 4 + j][p] = fmaf(wvs[j], avs[p], acc[og * 4 + j][p]);
            }
        }
    }

    float sc = 1.f;
    if (ACT == 2) sc = softplus_(__ldg(alpha));
    float* ob = out + (size_t)b * COUT * XS + p0 + po;
#pragma unroll
    for (int o = 0; o < TO; o++) {
        float bv = __ldg(&bias[oo + o]);
        float4 v;
        v.x = acc[o][0] + bv; v.y = acc[o][1] + bv;
        v.z = acc[o][2] + bv; v.w = acc[o][3] + bv;
        if (ACT == 1) { v.x = gelu_(v.x); v.y = gelu_(v.y); v.z = gelu_(v.z); v.w = gelu_(v.w); }
        if (ACT == 2) { v.x *= sc; v.y *= sc; v.z *= sc; v.w *= sc; }
        *(float4*)&ob[(size_t)(oo + o) * XS] = v;
    }
}

// ------------------- forward DFT (split-K partial GEMM) -------------------
__global__ void __launch_bounds__(256) fdft_kernel() {
    const int rt = blockIdx.x;     // 0..31 : row tiles (h rows then g rows)
    const int ks = blockIdx.y;     // 0..16 : K slices
    const float* src = (rt < 16) ? d_h + (size_t)rt * 64 * XS
                                 : d_g + (size_t)(rt - 16) * 64 * XS;
    const int kbase0 = ks * 1024;
    const int klen   = (ks == 16) ? 32 : 1024;

    __shared__ float sa[16][66];
    __shared__ float sb[16][128];
    const int tid = threadIdx.x;
    const int mo = (tid & 31) * 4;
    const int ro = (tid >> 5) * 8;

    float acc[8][4];
#pragma unroll
    for (int r = 0; r < 8; r++)
#pragma unroll
        for (int p = 0; p < 4; p++) acc[r][p] = 0.f;

    for (int kk = 0; kk < klen; kk += 16) {
        const int kb = kbase0 + kk;
        __syncthreads();
#pragma unroll
        for (int l = 0; l < 4; l++) {
            int idx = l * 256 + tid;
            int r = idx >> 4, k = idx & 15;
            sa[k][r] = src[(size_t)r * XS + kb + k];
        }
#pragma unroll
        for (int l = 0; l < 8; l++) {
            int idx = l * 256 + tid;
            int k = idx >> 7, m = idx & 127;
            sb[k][m] = d_ftab[(size_t)(kb + k) * 128 + m];
        }
        __syncthreads();
#pragma unroll
        for (int k = 0; k < 16; k++) {
            float4 bv = *(const float4*)&sb[k][mo];
            float bvs[4] = {bv.x, bv.y, bv.z, bv.w};
#pragma unroll
            for (int r = 0; r < 8; r++) {
                float a = sa[k][ro + r];
#pragma unroll
                for (int p = 0; p < 4; p++)
                    acc[r][p] = fmaf(a, bvs[p], acc[r][p]);
            }
        }
    }
#pragma unroll
    for (int r = 0; r < 8; r++) {
        float4 v = make_float4(acc[r][0], acc[r][1], acc[r][2], acc[r][3]);
        *(float4*)&d_part[((size_t)ks * 2048 + rt * 64 + ro + r) * 128 + mo] = v;
    }
}

__global__ void reduce_kernel() {
    int idx = blockIdx.x * 256 + threadIdx.x;   // 262144
    float s = 0.f;
#pragma unroll
    for (int k = 0; k < 17; k++) s += d_part[(size_t)k * 262144 + idx];
    d_fw[idx] = s;
}

// ------------------- mode mix + ETD coefficients -------------------
__global__ void __launch_bounds__(512) modemix_kernel(const float* __restrict__ mix_re,
                                                      const float* __restrict__ mix_im,
                                                      const float* __restrict__ log_decay,
                                                      int blk) {
    __shared__ float sg[64 * 128];
    const int b  = blockIdx.x;      // 0..15
    const int og = blockIdx.y;      // 0..7
    const int tid = threadIdx.x;
#pragma unroll
    for (int l = 0; l < 16; l++) {
        int idx = l * 512 + tid;
        sg[idx] = d_fw[(size_t)(1024 + b * 64) * 128 + idx];
    }
    __syncthreads();
    const int m = tid & 63, ol = tid >> 6;
    const int o = og * 8 + ol;
    const float* mr = mix_re + (size_t)blk * 262144 + o * 64 + m;
    const float* mi = mix_im + (size_t)blk * 262144 + o * 64 + m;
    float ar = 0.f, ai = 0.f;
#pragma unroll 4
    for (int i = 0; i < 64; i++) {
        float2 gh = *(const float2*)&sg[i * 128 + 2 * m];
        float r_ = __ldg(&mr[(size_t)i * 4096]);
        float i_ = __ldg(&mi[(size_t)i * 4096]);
        ar = fmaf(gh.x, r_, ar); ar = fmaf(-gh.y, i_, ar);
        ai = fmaf(gh.x, i_, ai); ai = fmaf( gh.y, r_, ai);
    }
    float ld = __ldg(&log_decay[((size_t)blk * 64 + o) * 64 + m]);
    float z  = -softplus_(ld);
    float ez = expf(z);
    float phi = (fabsf(z) < 1e-6f) ? (1.f + 0.5f * z + z * z * (1.f / 6.f))
                                   : (expm1f(z) / z);
    float gq = (float)m * (1.f / 63.f);
    float r2 = gq * gq + 1e-12f;
    float r8 = r2 * r2; r8 = r8 * r8;
    float pf = phi * expf(-2.f * r8);

    size_t vrow = ((size_t)b * 64 + o) * 128;
    float vr = d_fw[vrow + 2 * m], vi = d_fw[vrow + 2 * m + 1];
    float outr = fmaf(ez, vr, pf * ar);
    float outi = fmaf(ez, vi, pf * ai);
    const float inv = 1.0f / 16386.0f;
    d_outm[vrow + 2 * m]     = (m == 0) ? outr * inv : 2.f * outr * inv;
    d_outm[vrow + 2 * m + 1] = (m == 0) ? 0.f        : -2.f * outi * inv;
}

// ------------------- inverse DFT + skip + activation (writes h) -------------------
__global__ void __launch_bounds__(256) idft_kernel(const float* __restrict__ alpha_w, int act) {
    const int x0   = blockIdx.x * 128;
    const int row0 = blockIdx.y * 64;
    __shared__ float sc_[16][66];
    __shared__ float st [16][128];
    const int tid = threadIdx.x;
    const int xo = (tid & 31) * 4;
    const int ro = (tid >> 5) * 8;

    float acc[8][4];
#pragma unroll
    for (int r = 0; r < 8; r++)
#pragma unroll
        for (int p = 0; p < 4; p++) acc[r][p] = 0.f;

    for (int kb = 0; kb < 128; kb += 16) {
        __syncthreads();
#pragma unroll
        for (int l = 0; l < 4; l++) {
            int idx = l * 256 + tid;
            int r = idx >> 4, k = idx & 15;
            sc_[k][r] = d_outm[(size_t)(row0 + r) * 128 + kb + k];
        }
#pragma unroll
        for (int l = 0; l < 8; l++) {
            int idx = l * 256 + tid;
            int k = idx >> 7, xl = idx & 127;
            st[k][xl] = d_itab[(size_t)(kb + k) * XS + x0 + xl];
        }
        __syncthreads();
#pragma unroll
        for (int k = 0; k < 16; k++) {
            float4 tv = *(const float4*)&st[k][xo];
            float tvs[4] = {tv.x, tv.y, tv.z, tv.w};
#pragma unroll
            for (int r = 0; r < 8; r++) {
                float cv = sc_[k][ro + r];
#pragma unroll
                for (int p = 0; p < 4; p++)
                    acc[r][p] = fmaf(cv, tvs[p], acc[r][p]);
            }
        }
    }
    const float aw = softplus_(__ldg(alpha_w));
#pragma unroll
    for (int r = 0; r < 8; r++) {
        size_t off = (size_t)(row0 + ro + r) * XS + x0 + xo;
        float4 w = *(const float4*)&d_wout[off];
        float4 v;
        v.x = fmaf(aw, w.x, acc[r][0]);
        v.y = fmaf(aw, w.y, acc[r][1]);
        v.z = fmaf(aw, w.z, acc[r][2]);
        v.w = fmaf(aw, w.w, acc[r][3]);
        if (act) { v.x = gelu_(v.x); v.y = gelu_(v.y); v.z = gelu_(v.z); v.w = gelu_(v.w); }
        *(float4*)&d_h[off] = v;
    }
}

// ------------------- fc2 -------------------
__global__ void __launch_bounds__(128) fc2_kernel(const float* __restrict__ w,
                                                  const float* __restrict__ bias,
                                                  float* __restrict__ out) {
    __shared__ float sw[3][128];
    int tid = threadIdx.x;
    for (int l = tid; l < 384; l += 128) sw[l >> 7][l & 127] = w[l];
    __syncthreads();
    int b = blockIdx.y;
    int x = blockIdx.x * 128 + tid;
    float a0 = __ldg(&bias[0]), a1 = __ldg(&bias[1]), a2 = __ldg(&bias[2]);
#pragma unroll 4
    for (int j = 0; j < 128; j++) {
        float v = d_gmid[((size_t)b * 128 + j) * XS + x];
        a0 = fmaf(v, sw[0][j], a0);
        a1 = fmaf(v, sw[1][j], a1);
        a2 = fmaf(v, sw[2][j], a2);
    }
    size_t o = ((size_t)b * NXV + x) * 3;
    out[o] = a0; out[o + 1] = a1; out[o + 2] = a2;
}

// ------------------- launch -------------------
extern "C" void kernel_launch(void* const* d_in, const int* in_sizes, int n_in,
                              void* d_out, int out_size) {
    const float* x_in   = (const float*)d_in[0];
    const float* grid   = (const float*)d_in[1];
    const float* fc0_w  = (const float*)d_in[2];
    const float* fc0_b  = (const float*)d_in[3];
    const float* fc1_w  = (const float*)d_in[4];
    const float* fc1_b  = (const float*)d_in[5];
    const float* fc2_w  = (const float*)d_in[6];
    const float* fc2_b  = (const float*)d_in[7];
    const float* g_w1   = (const float*)d_in[8];
    const float* g_b1   = (const float*)d_in[9];
    const float* g_w2   = (const float*)d_in[10];
    const float* g_b2   = (const float*)d_in[11];
    const float* w_w    = (const float*)d_in[12];
    const float* w_b    = (const float*)d_in[13];
    const float* ldcy   = (const float*)d_in[14];
    const float* mix_re = (const float*)d_in[15];
    const float* mix_im = (const float*)d_in[16];
    const float* aw     = (const float*)d_in[17];
    const float* ag     = (const float*)d_in[18];

    float *ph, *pg, *pgmid, *pwout, *pw1T, *pw2T, *pwwT, *pfc1T;
    cudaGetSymbolAddress((void**)&ph,    d_h);
    cudaGetSymbolAddress((void**)&pg,    d_g);
    cudaGetSymbolAddress((void**)&pgmid, d_gmid);
    cudaGetSymbolAddress((void**)&pwout, d_wout);
    cudaGetSymbolAddress((void**)&pw1T,  d_w1T);
    cudaGetSymbolAddress((void**)&pw2T,  d_w2T);
    cudaGetSymbolAddress((void**)&pwwT,  d_wwT);
    cudaGetSymbolAddress((void**)&pfc1T, d_fc1T);

    init_ftab_kernel<<<(KPAD * 128 + 255) / 256, 256>>>();
    init_itab_kernel<<<(128 * XS + 255) / 256, 256>>>();
    prep_weights_kernel<<<352, 256>>>(g_w1, g_w2, w_w, fc1_w);
    zero_tail_kernel<<<512, 256>>>();
    fc0_kernel<<<dim3(128, 16), 128>>>(x_in, grid, fc0_w, fc0_b);

    for (int i = 0; i < 4; i++) {
        conv1x1_kernel<64, 128, 1><<<dim3(129, 16), 256>>>(
            ph, pw1T + i * 8192, g_b1 + i * 128, pgmid, nullptr);
        conv1x1_kernel<128, 64, 2><<<dim3(129, 16), 256>>>(
            pgmid, pw2T + i * 8192, g_b2 + i * 64, pg, ag);
        conv1x1_kernel<64, 64, 0><<<dim3(129, 16), 256>>>(
            ph, pwwT + i * 4096, w_b + i * 64, pwout, nullptr);
        fdft_kernel<<<dim3(32, 17), 256>>>();
        reduce_kernel<<<1024, 256>>>();
        modemix_kernel<<<dim3(16, 8), 512>>>(mix_re, mix_im, ldcy, i);
        idft_kernel<<<dim3(129, 16), 256>>>(aw, (i < 3) ? 1 : 0);
    }

    conv1x1_kernel<64, 128, 1><<<dim3(128, 16), 256>>>(
        ph, pfc1T, fc1_b, pgmid, nullptr);
    fc2_kernel<<<dim3(128, 16), 128>>>(fc2_w, fc2_b, (float*)d_out);
}

// round 3
// speedup vs baseline: 1.1948x; 1.1948x over previous
#include <cuda_runtime.h>
#include <math.h>
#include <stdint.h>

#define XP    16386
#define XS    16512          // row stride (129*128)
#define NXV   16384
#define KPAD  16416          // 17 K-slices: 16*1024 + 32
#define NB    16
#define WCH   64
#define HCH   128

// ------------------- static device buffers -------------------
__device__ float d_h   [(size_t)NB * WCH * XS];
__device__ float d_g   [(size_t)NB * WCH * XS];
__device__ float d_gmid[(size_t)NB * HCH * XS];
__device__ float d_wout[(size_t)NB * WCH * XS];
__device__ float d_ftab[(size_t)KPAD * 128];     // [x][2m]=cos, [2m+1]=-sin
__device__ float d_itab[(size_t)128 * XS];       // [2m][x]=cos, [2m+1][x]=sin
__device__ float d_part[(size_t)17 * 2048 * 128];
__device__ float d_fw  [2048 * 128];             // rows 0..1023 v_hat(h), 1024..2047 g_hat
__device__ float d_outm[1024 * 128];             // scaled inverse-DFT coefficients
__device__ float d_w1T [4 * 64 * 128];
__device__ float d_w2T [4 * 128 * 64];
__device__ float d_wwT [4 * 64 * 64];
__device__ float d_fc1T[64 * 128];

// ------------------- f32x2 packed helpers -------------------
__device__ __forceinline__ uint64_t pack2(float lo, float hi) {
    uint64_t r;
    asm("mov.b64 %0, {%1, %2};" : "=l"(r) : "f"(lo), "f"(hi));
    return r;
}
__device__ __forceinline__ void unpack2(uint64_t v, float& lo, float& hi) {
    asm("mov.b64 {%0, %1}, %2;" : "=f"(lo), "=f"(hi) : "l"(v));
}
#define FMA2(d, a, b) \
    asm("fma.rn.f32x2 %0, %1, %2, %0;" : "+l"(d) : "l"(a), "l"(b))

// ------------------- helpers -------------------
__device__ __forceinline__ float softplus_(float x) {
    return (x > 20.f) ? x : log1pf(expf(x));
}
__device__ __forceinline__ float gelu_(float v) {
    return 0.5f * v * (1.0f + erff(v * 0.70710678118654752f));
}

// ------------------- table init (exact integer phase, fp32 sincospif) -------------------
__global__ void init_ftab_kernel() {
    int idx = blockIdx.x * 256 + threadIdx.x;
    if (idx >= KPAD * 128) return;
    int x = idx >> 7, t = idx & 127, m = t >> 1;
    float v = 0.f;
    if (x < XP) {
        int u = (x * m) % XP;
        float s, c;
        sincospif(2.0f * (float)u / (float)XP, &s, &c);
        v = (t & 1) ? -s : c;
    }
    d_ftab[idx] = v;
}

__global__ void init_itab_kernel() {
    int idx = blockIdx.x * 256 + threadIdx.x;
    if (idx >= 128 * XS) return;
    int t = idx / XS, x = idx - t * XS, m = t >> 1;
    float v = 0.f;
    if (x < XP) {
        int u = (x * m) % XP;
        float s, c;
        sincospif(2.0f * (float)u / (float)XP, &s, &c);
        v = (t & 1) ? s : c;
    }
    d_itab[idx] = v;
}

// ------------------- weight transposes -------------------
__global__ void prep_weights_kernel(const float* __restrict__ g_w1,
                                    const float* __restrict__ g_w2,
                                    const float* __restrict__ w_w,
                                    const float* __restrict__ fc1_w) {
    int idx = blockIdx.x * 256 + threadIdx.x;
    if (idx < 32768) {                           // w1T[i][c][j] = g_w1[i][j][c]
        int i = idx >> 13, r = idx & 8191, c = r >> 7, j = r & 127;
        d_w1T[idx] = g_w1[(i * 128 + j) * 64 + c];
    } else if (idx < 65536) {                    // w2T[i][j][o] = g_w2[i][o][j]
        int t = idx - 32768;
        int i = t >> 13, r = t & 8191, j = r >> 6, o = r & 63;
        d_w2T[t] = g_w2[(i * 64 + o) * 128 + j];
    } else if (idx < 81920) {                    // wwT[i][c][o] = w_w[i][o][c]
        int t = idx - 65536;
        int i = t >> 12, r = t & 4095, c = r >> 6, o = r & 63;
        d_wwT[t] = w_w[(i * 64 + o) * 64 + c];
    } else if (idx < 90112) {                    // fc1T[c][j] = fc1_w[j][c]
        int t = idx - 81920;
        int c = t >> 7, j = t & 127;
        d_fc1T[t] = fc1_w[j * 64 + c];
    }
}

__global__ void zero_tail_kernel() {
    int idx = blockIdx.x * 256 + threadIdx.x;    // 1024 rows x 128 tail cols
    int row = idx >> 7, col = NXV + (idx & 127);
    d_h[(size_t)row * XS + col] = 0.f;
}

// ------------------- fc0 -------------------
__global__ void __launch_bounds__(128) fc0_kernel(const float* __restrict__ xin,
                                                  const float* __restrict__ gin,
                                                  const float* __restrict__ w,
                                                  const float* __restrict__ bias) {
    __shared__ float sw[64 * 32];
    __shared__ float sb[64];
    int tid = threadIdx.x;
    for (int l = tid; l < 64 * 31; l += 128) {
        int wo = l / 31, c = l - wo * 31;
        sw[wo * 32 + c] = w[l];
    }
    if (tid < 64) sb[tid] = bias[tid];
    __syncthreads();
    int b = blockIdx.y;
    int x = blockIdx.x * 128 + tid;
    float rin[31];
    const float* xi = xin + ((size_t)b * NXV + x) * 30;
#pragma unroll
    for (int c = 0; c < 30; c++) rin[c] = __ldg(&xi[c]);
    rin[30] = __ldg(&gin[(size_t)b * NXV + x]);
    for (int wo = 0; wo < 64; wo++) {
        float acc = sb[wo];
#pragma unroll
        for (int c = 0; c < 31; c++) acc = fmaf(rin[c], sw[wo * 32 + c], acc);
        d_h[(size_t)(b * 64 + wo) * XS + x] = acc;
    }
}

// ------------------- generic 1x1 conv, packed f32x2 -------------------
// ACT: 0=none, 1=gelu, 2=scale by softplus(*alpha) after bias
template<int CIN, int COUT, int ACT>
__global__ void __launch_bounds__(256) conv1x1_kernel(
    const float* __restrict__ in,    // [b*CIN + c][XS]
    const float* __restrict__ wT,    // [CIN][COUT]
    const float* __restrict__ bias,  // [COUT]
    float* __restrict__ out,         // [b*COUT + o][XS]
    const float* __restrict__ alpha)
{
    constexpr int TO = COUT / 8;     // outputs per thread (16 or 8)
    constexpr int TP = TO / 2;       // output pairs
    __shared__ float si [16][128];
    __shared__ float swt[16][COUT];
    const int b   = blockIdx.y;
    const int p0  = blockIdx.x * 128;
    const int tid = threadIdx.x;
    const int po  = (tid & 31) * 4;
    const int oo  = (tid >> 5) * TO;

    uint64_t accp[TP][4];            // [o-pair][position], lanes = (o even, o odd)
#pragma unroll
    for (int o = 0; o < TP; o++)
#pragma unroll
        for (int p = 0; p < 4; p++) accp[o][p] = 0ull;

    const float* inb = in + (size_t)b * CIN * XS + p0;
    for (int c0 = 0; c0 < CIN; c0 += 16) {
        __syncthreads();
#pragma unroll
        for (int l = 0; l < 8; l++) {
            int idx = l * 256 + tid;
            int k = idx >> 7, p = idx & 127;
            si[k][p] = inb[(size_t)(c0 + k) * XS + p];
        }
#pragma unroll
        for (int l = 0; l < (16 * COUT) / 256; l++) {
            int idx = l * 256 + tid;
            int k = idx / COUT, o = idx - k * COUT;
            swt[k][o] = wT[(size_t)(c0 + k) * COUT + o];
        }
        __syncthreads();
#pragma unroll
        for (int k = 0; k < 16; k++) {
            float4 av = *(const float4*)&si[k][po];
            uint64_t pa[4];
            pa[0] = pack2(av.x, av.x); pa[1] = pack2(av.y, av.y);
            pa[2] = pack2(av.z, av.z); pa[3] = pack2(av.w, av.w);
#pragma unroll
            for (int o2 = 0; o2 < TP; o2++) {
                uint64_t wv = *(const uint64_t*)&swt[k][oo + 2 * o2];
#pragma unroll
                for (int p = 0; p < 4; p++) FMA2(accp[o2][p], wv, pa[p]);
            }
        }
    }

    float sc = 1.f;
    if (ACT == 2) sc = softplus_(__ldg(alpha));
    float* ob = out + (size_t)b * COUT * XS + p0 + po;
#pragma unroll
    for (int o2 = 0; o2 < TP; o2++) {
        float blo = __ldg(&bias[oo + 2 * o2]);
        float bhi = __ldg(&bias[oo + 2 * o2 + 1]);
        float4 vlo, vhi;
        float* plo = &vlo.x; float* phi_ = &vhi.x;
#pragma unroll
        for (int p = 0; p < 4; p++) {
            float a, c;
            unpack2(accp[o2][p], a, c);
            plo[p] = a + blo; phi_[p] = c + bhi;
            if (ACT == 1) { plo[p] = gelu_(plo[p]); phi_[p] = gelu_(phi_[p]); }
            if (ACT == 2) { plo[p] *= sc; phi_[p] *= sc; }
        }
        *(float4*)&ob[(size_t)(oo + 2 * o2) * XS]     = vlo;
        *(float4*)&ob[(size_t)(oo + 2 * o2 + 1) * XS] = vhi;
    }
}

// ------------------- forward DFT (split-K partial GEMM, packed) -------------------
__global__ void __launch_bounds__(256) fdft_kernel() {
    const int rt = blockIdx.x;     // 0..31 : row tiles (h rows then g rows)
    const int ks = blockIdx.y;     // 0..16 : K slices
    const float* src = (rt < 16) ? d_h + (size_t)rt * 64 * XS
                                 : d_g + (size_t)(rt - 16) * 64 * XS;
    const int kbase0 = ks * 1024;
    const int klen   = (ks == 16) ? 32 : 1024;

    __shared__ float sa[16][66];
    __shared__ float sb[16][128];
    const int tid = threadIdx.x;
    const int mo = (tid & 31) * 4;
    const int ro = (tid >> 5) * 8;

    uint64_t accp[4][4];           // [row-pair][mode], lanes = (row even, row odd)
#pragma unroll
    for (int r = 0; r < 4; r++)
#pragma unroll
        for (int p = 0; p < 4; p++) accp[r][p] = 0ull;

    for (int kk = 0; kk < klen; kk += 16) {
        const int kb = kbase0 + kk;
        __syncthreads();
#pragma unroll
        for (int l = 0; l < 4; l++) {
            int idx = l * 256 + tid;
            int r = idx >> 4, k = idx & 15;
            sa[k][r] = src[(size_t)r * XS + kb + k];
        }
#pragma unroll
        for (int l = 0; l < 8; l++) {
            int idx = l * 256 + tid;
            int k = idx >> 7, m = idx & 127;
            sb[k][m] = d_ftab[(size_t)(kb + k) * 128 + m];
        }
        __syncthreads();
#pragma unroll
        for (int k = 0; k < 16; k++) {
            float4 bv = *(const float4*)&sb[k][mo];
            uint64_t pb[4];
            pb[0] = pack2(bv.x, bv.x); pb[1] = pack2(bv.y, bv.y);
            pb[2] = pack2(bv.z, bv.z); pb[3] = pack2(bv.w, bv.w);
#pragma unroll
            for (int r2 = 0; r2 < 4; r2++) {
                uint64_t a2 = *(const uint64_t*)&sa[k][ro + 2 * r2];
#pragma unroll
                for (int p = 0; p < 4; p++) FMA2(accp[r2][p], a2, pb[p]);
            }
        }
    }
#pragma unroll
    for (int r2 = 0; r2 < 4; r2++) {
        float4 vlo, vhi;
        unpack2(accp[r2][0], vlo.x, vhi.x);
        unpack2(accp[r2][1], vlo.y, vhi.y);
        unpack2(accp[r2][2], vlo.z, vhi.z);
        unpack2(accp[r2][3], vlo.w, vhi.w);
        *(float4*)&d_part[((size_t)ks * 2048 + rt * 64 + ro + 2 * r2) * 128 + mo]     = vlo;
        *(float4*)&d_part[((size_t)ks * 2048 + rt * 64 + ro + 2 * r2 + 1) * 128 + mo] = vhi;
    }
}

__global__ void reduce_kernel() {
    int idx = blockIdx.x * 256 + threadIdx.x;   // 262144
    float s = 0.f;
#pragma unroll
    for (int k = 0; k < 17; k++) s += d_part[(size_t)k * 262144 + idx];
    d_fw[idx] = s;
}

// ------------------- mode mix + ETD coefficients -------------------
__global__ void __launch_bounds__(512) modemix_kernel(const float* __restrict__ mix_re,
                                                      const float* __restrict__ mix_im,
                                                      const float* __restrict__ log_decay,
                                                      int blk) {
    __shared__ float sg[64 * 128];
    const int b  = blockIdx.x;      // 0..15
    const int og = blockIdx.y;      // 0..7
    const int tid = threadIdx.x;
#pragma unroll
    for (int l = 0; l < 16; l++) {
        int idx = l * 512 + tid;
        sg[idx] = d_fw[(size_t)(1024 + b * 64) * 128 + idx];
    }
    __syncthreads();
    const int m = tid & 63, ol = tid >> 6;
    const int o = og * 8 + ol;
    const float* mr = mix_re + (size_t)blk * 262144 + o * 64 + m;
    const float* mi = mix_im + (size_t)blk * 262144 + o * 64 + m;
    float ar = 0.f, ai = 0.f;
#pragma unroll 4
    for (int i = 0; i < 64; i++) {
        float2 gh = *(const float2*)&sg[i * 128 + 2 * m];
        float r_ = __ldg(&mr[(size_t)i * 4096]);
        float i_ = __ldg(&mi[(size_t)i * 4096]);
        ar = fmaf(gh.x, r_, ar); ar = fmaf(-gh.y, i_, ar);
        ai = fmaf(gh.x, i_, ai); ai = fmaf( gh.y, r_, ai);
    }
    float ld = __ldg(&log_decay[((size_t)blk * 64 + o) * 64 + m]);
    float z  = -softplus_(ld);
    float ez = expf(z);
    float phi = (fabsf(z) < 1e-6f) ? (1.f + 0.5f * z + z * z * (1.f / 6.f))
                                   : (expm1f(z) / z);
    float gq = (float)m * (1.f / 63.f);
    float r2 = gq * gq + 1e-12f;
    float r8 = r2 * r2; r8 = r8 * r8;
    float pf = phi * expf(-2.f * r8);

    size_t vrow = ((size_t)b * 64 + o) * 128;
    float vr = d_fw[vrow + 2 * m], vi = d_fw[vrow + 2 * m + 1];
    float outr = fmaf(ez, vr, pf * ar);
    float outi = fmaf(ez, vi, pf * ai);
    const float inv = 1.0f / 16386.0f;
    d_outm[vrow + 2 * m]     = (m == 0) ? outr * inv : 2.f * outr * inv;
    d_outm[vrow + 2 * m + 1] = (m == 0) ? 0.f        : -2.f * outi * inv;
}

// ------------------- inverse DFT + skip + activation (packed) -------------------
__global__ void __launch_bounds__(256) idft_kernel(const float* __restrict__ alpha_w, int act) {
    const int x0   = blockIdx.x * 128;
    const int row0 = blockIdx.y * 64;
    __shared__ float sc_[16][66];
    __shared__ float st [16][128];
    const int tid = threadIdx.x;
    const int xo = (tid & 31) * 4;
    const int ro = (tid >> 5) * 8;

    uint64_t accp[4][4];           // [row-pair][x], lanes = (row even, row odd)
#pragma unroll
    for (int r = 0; r < 4; r++)
#pragma unroll
        for (int p = 0; p < 4; p++) accp[r][p] = 0ull;

    for (int kb = 0; kb < 128; kb += 16) {
        __syncthreads();
#pragma unroll
        for (int l = 0; l < 4; l++) {
            int idx = l * 256 + tid;
            int r = idx >> 4, k = idx & 15;
            sc_[k][r] = d_outm[(size_t)(row0 + r) * 128 + kb + k];
        }
#pragma unroll
        for (int l = 0; l < 8; l++) {
            int idx = l * 256 + tid;
            int k = idx >> 7, xl = idx & 127;
            st[k][xl] = d_itab[(size_t)(kb + k) * XS + x0 + xl];
        }
        __syncthreads();
#pragma unroll
        for (int k = 0; k < 16; k++) {
            float4 tv = *(const float4*)&st[k][xo];
            uint64_t pt[4];
            pt[0] = pack2(tv.x, tv.x); pt[1] = pack2(tv.y, tv.y);
            pt[2] = pack2(tv.z, tv.z); pt[3] = pack2(tv.w, tv.w);
#pragma unroll
            for (int r2 = 0; r2 < 4; r2++) {
                uint64_t c2 = *(const uint64_t*)&sc_[k][ro + 2 * r2];
#pragma unroll
                for (int p = 0; p < 4; p++) FMA2(accp[r2][p], c2, pt[p]);
            }
        }
    }
    const float aw = softplus_(__ldg(alpha_w));
#pragma unroll
    for (int r2 = 0; r2 < 4; r2++) {
        float4 vlo, vhi;
        unpack2(accp[r2][0], vlo.x, vhi.x);
        unpack2(accp[r2][1], vlo.y, vhi.y);
        unpack2(accp[r2][2], vlo.z, vhi.z);
        unpack2(accp[r2][3], vlo.w, vhi.w);
        size_t off0 = (size_t)(row0 + ro + 2 * r2) * XS + x0 + xo;
        size_t off1 = off0 + XS;
        float4 w0 = *(const float4*)&d_wout[off0];
        float4 w1 = *(const float4*)&d_wout[off1];
        vlo.x = fmaf(aw, w0.x, vlo.x); vlo.y = fmaf(aw, w0.y, vlo.y);
        vlo.z = fmaf(aw, w0.z, vlo.z); vlo.w = fmaf(aw, w0.w, vlo.w);
        vhi.x = fmaf(aw, w1.x, vhi.x); vhi.y = fmaf(aw, w1.y, vhi.y);
        vhi.z = fmaf(aw, w1.z, vhi.z); vhi.w = fmaf(aw, w1.w, vhi.w);
        if (act) {
            vlo.x = gelu_(vlo.x); vlo.y = gelu_(vlo.y); vlo.z = gelu_(vlo.z); vlo.w = gelu_(vlo.w);
            vhi.x = gelu_(vhi.x); vhi.y = gelu_(vhi.y); vhi.z = gelu_(vhi.z); vhi.w = gelu_(vhi.w);
        }
        *(float4*)&d_h[off0] = vlo;
        *(float4*)&d_h[off1] = vhi;
    }
}

// ------------------- fc2 -------------------
__global__ void __launch_bounds__(128) fc2_kernel(const float* __restrict__ w,
                                                  const float* __restrict__ bias,
                                                  float* __restrict__ out) {
    __shared__ float sw[3][128];
    int tid = threadIdx.x;
    for (int l = tid; l < 384; l += 128) sw[l >> 7][l & 127] = w[l];
    __syncthreads();
    int b = blockIdx.y;
    int x = blockIdx.x * 128 + tid;
    float a0 = __ldg(&bias[0]), a1 = __ldg(&bias[1]), a2 = __ldg(&bias[2]);
#pragma unroll 4
    for (int j = 0; j < 128; j++) {
        float v = d_gmid[((size_t)b * 128 + j) * XS + x];
        a0 = fmaf(v, sw[0][j], a0);
        a1 = fmaf(v, sw[1][j], a1);
        a2 = fmaf(v, sw[2][j], a2);
    }
    size_t o = ((size_t)b * NXV + x) * 3;
    out[o] = a0; out[o + 1] = a1; out[o + 2] = a2;
}

// ------------------- launch -------------------
extern "C" void kernel_launch(void* const* d_in, const int* in_sizes, int n_in,
                              void* d_out, int out_size) {
    const float* x_in   = (const float*)d_in[0];
    const float* grid   = (const float*)d_in[1];
    const float* fc0_w  = (const float*)d_in[2];
    const float* fc0_b  = (const float*)d_in[3];
    const float* fc1_w  = (const float*)d_in[4];
    const float* fc1_b  = (const float*)d_in[5];
    const float* fc2_w  = (const float*)d_in[6];
    const float* fc2_b  = (const float*)d_in[7];
    const float* g_w1   = (const float*)d_in[8];
    const float* g_b1   = (const float*)d_in[9];
    const float* g_w2   = (const float*)d_in[10];
    const float* g_b2   = (const float*)d_in[11];
    const float* w_w    = (const float*)d_in[12];
    const float* w_b    = (const float*)d_in[13];
    const float* ldcy   = (const float*)d_in[14];
    const float* mix_re = (const float*)d_in[15];
    const float* mix_im = (const float*)d_in[16];
    const float* aw     = (const float*)d_in[17];
    const float* ag     = (const float*)d_in[18];

    float *ph, *pg, *pgmid, *pwout, *pw1T, *pw2T, *pwwT, *pfc1T;
    cudaGetSymbolAddress((void**)&ph,    d_h);
    cudaGetSymbolAddress((void**)&pg,    d_g);
    cudaGetSymbolAddress((void**)&pgmid, d_gmid);
    cudaGetSymbolAddress((void**)&pwout, d_wout);
    cudaGetSymbolAddress((void**)&pw1T,  d_w1T);
    cudaGetSymbolAddress((void**)&pw2T,  d_w2T);
    cudaGetSymbolAddress((void**)&pwwT,  d_wwT);
    cudaGetSymbolAddress((void**)&pfc1T, d_fc1T);

    init_ftab_kernel<<<(KPAD * 128 + 255) / 256, 256>>>();
    init_itab_kernel<<<(128 * XS + 255) / 256, 256>>>();
    prep_weights_kernel<<<352, 256>>>(g_w1, g_w2, w_w, fc1_w);
    zero_tail_kernel<<<512, 256>>>();
    fc0_kernel<<<dim3(128, 16), 128>>>(x_in, grid, fc0_w, fc0_b);

    for (int i = 0; i < 4; i++) {
        conv1x1_kernel<64, 128, 1><<<dim3(129, 16), 256>>>(
            ph, pw1T + i * 8192, g_b1 + i * 128, pgmid, nullptr);
        conv1x1_kernel<128, 64, 2><<<dim3(129, 16), 256>>>(
            pgmid, pw2T + i * 8192, g_b2 + i * 64, pg, ag);
        conv1x1_kernel<64, 64, 0><<<dim3(129, 16), 256>>>(
            ph, pwwT + i * 4096, w_b + i * 64, pwout, nullptr);
        fdft_kernel<<<dim3(32, 17), 256>>>();
        reduce_kernel<<<1024, 256>>>();
        modemix_kernel<<<dim3(16, 8), 512>>>(mix_re, mix_im, ldcy, i);
        idft_kernel<<<dim3(129, 16), 256>>>(aw, (i < 3) ? 1 : 0);
    }

    conv1x1_kernel<64, 128, 1><<<dim3(128, 16), 256>>>(
        ph, pfc1T, fc1_b, pgmid, nullptr);
    fc2_kernel<<<dim3(128, 16), 128>>>(fc2_w, fc2_b, (float*)d_out);
}